// round 3
// baseline (speedup 1.0000x reference)
#include <cuda_runtime.h>

#define NSLICE 64      // B*C
#define SEQ    1024    // N
#define HD     128     // D
#define BM     64
#define BN     64
#define EPSV   1e-7f

// Scratch for per-row norms (alloc-free rule: __device__ global)
__device__ float g_norms[NSLICE * SEQ];

// ---------------- packed f32x2 helpers ----------------
__device__ __forceinline__ void ffma2(unsigned long long& d,
                                      unsigned long long a,
                                      unsigned long long b) {
    asm("fma.rn.f32x2 %0, %1, %2, %0;" : "+l"(d) : "l"(a), "l"(b));
}
__device__ __forceinline__ unsigned long long dup2(float x) {
    unsigned long long r;
    asm("mov.b64 %0, {%1, %1};" : "=l"(r) : "f"(x));
    return r;
}
__device__ __forceinline__ float hadd2(unsigned long long p) {
    float lo, hi;
    asm("mov.b64 {%0, %1}, %2;" : "=f"(lo), "=f"(hi) : "l"(p));
    return lo + hi;
}

// ---------------- norms precompute: 1 warp per row ----------------
__global__ __launch_bounds__(256) void norms_kernel(const float* __restrict__ x) {
    int row  = blockIdx.x * 8 + (threadIdx.x >> 5);   // 65536 rows total
    int lane = threadIdx.x & 31;
    const float4* xr = reinterpret_cast<const float4*>(x + (size_t)row * HD);
    float4 v = xr[lane];                              // 32 lanes * 4 = 128
    float s = v.x * v.x + v.y * v.y + v.z * v.z + v.w * v.w;
#pragma unroll
    for (int o = 16; o; o >>= 1) s += __shfl_xor_sync(0xffffffffu, s, o);
    if (lane == 0) g_norms[row] = sqrtf(s);
}

// ---------------- fused cosine attention ----------------
// smem layout (floats):
//   Qs [64][128]  row-major               @ 0      (8192)
//   Ks [64][128]  16B-block swizzled      @ 8192   (8192)   (K tile, also V)
//   Pt [64][64]   P^T, block swizzled     @ 16384  (4096)
//   qn [64]                               @ 20480
//   kn [64]                               @ 20544
// total 20608 floats = 82432 bytes
__global__ __launch_bounds__(256, 2) void cosatt_kernel(
    const float* __restrict__ x,
    const float* __restrict__ beta,
    float* __restrict__ out)
{
    extern __shared__ float sm[];
    float* Qs = sm;
    float* Ks = sm + 8192;
    float* Pt = sm + 16384;
    float* qn = sm + 20480;
    float* kn = sm + 20544;

    const int tid = threadIdx.x;
    const int tx  = tid & 15;
    const int ty  = tid >> 4;
    const int slice = blockIdx.y;
    const int qbase = blockIdx.x * BM;

    const float* xs  = x + (size_t)slice * SEQ * HD;
    const float* nrm = g_norms + slice * SEQ;

    // ---- load Q tile (row-major; reads are ty-broadcast so no swizzle needed)
    {
        const float4* src = reinterpret_cast<const float4*>(xs + (size_t)qbase * HD);
        float4* dst = reinterpret_cast<float4*>(Qs);
#pragma unroll
        for (int r = 0; r < 8; ++r) {
            int f = r * 256 + tid;          // row = f>>5 (warp-const), c4 = f&31 (=lane)
            dst[f] = src[f];
        }
        if (tid < BM) qn[tid] = nrm[qbase + tid];
    }

    // O accumulators: rows i = ty*4+ii ; cols {tx*4 + 2*p, 64 + tx*4 + 2*p} packed pairs
    unsigned long long Oacc[4][4];
#pragma unroll
    for (int a = 0; a < 4; ++a)
#pragma unroll
        for (int b = 0; b < 4; ++b) Oacc[a][b] = 0ull;

    for (int kt = 0; kt < SEQ / BN; ++kt) {
        const int kbase = kt * BN;
        __syncthreads();   // previous iteration's readers of Ks/kn/Pt are done

        // ---- load K tile, swizzled: phys block = c4 ^ ((row>>2)&7)
        {
            const float4* src = reinterpret_cast<const float4*>(xs + (size_t)kbase * HD);
#pragma unroll
            for (int r = 0; r < 8; ++r) {
                int f  = r * 256 + tid;
                int j  = f >> 5;
                int c4 = f & 31;
                int pc = c4 ^ ((j >> 2) & 7);
                reinterpret_cast<float4*>(Ks)[j * 32 + pc] = src[f];
            }
            if (tid < BN) kn[tid] = nrm[kbase + tid];
        }
        __syncthreads();

        // ---- GEMM1: S[i][j] = sum_d Q[i,d]*K[j,d], f32x2 packed along d
        unsigned long long Sacc[4][4];
#pragma unroll
        for (int a = 0; a < 4; ++a)
#pragma unroll
            for (int b = 0; b < 4; ++b) Sacc[a][b] = 0ull;

#pragma unroll 4
        for (int d4 = 0; d4 < 32; ++d4) {
            ulonglong2 qv[4], kv[4];
#pragma unroll
            for (int ii = 0; ii < 4; ++ii) {
                int i = ty * 4 + ii;
                qv[ii] = *reinterpret_cast<const ulonglong2*>(Qs + i * 128 + d4 * 4);
            }
#pragma unroll
            for (int jj = 0; jj < 4; ++jj) {
                int j  = tx * 4 + jj;
                int pc = d4 ^ ((j >> 2) & 7);
                kv[jj] = *reinterpret_cast<const ulonglong2*>(Ks + j * 128 + pc * 4);
            }
#pragma unroll
            for (int ii = 0; ii < 4; ++ii)
#pragma unroll
                for (int jj = 0; jj < 4; ++jj) {
                    ffma2(Sacc[ii][jj], qv[ii].x, kv[jj].x);
                    ffma2(Sacc[ii][jj], qv[ii].y, kv[jj].y);
                }
        }

        // ---- epilogue: cos -> sigmoid -> store P^T (swizzled: blk = (i>>2)^(j>>2))
#pragma unroll
        for (int ii = 0; ii < 4; ++ii) {
            int i = ty * 4 + ii;
            float qni = qn[i];
            float4 bv = *reinterpret_cast<const float4*>(
                beta + (size_t)(qbase + i) * SEQ + kbase + tx * 4);
            float bArr[4] = {bv.x, bv.y, bv.z, bv.w};
#pragma unroll
            for (int jj = 0; jj < 4; ++jj) {
                int j = tx * 4 + jj;
                float s = hadd2(Sacc[ii][jj]);
                float c = s / (qni * kn[j] + EPSV);
                float t = bArr[jj] * c;
                float p = 1.0f / (1.0f + __expf(-t));
                int blk = ty ^ tx;                      // (i>>2) ^ (j>>2)
                Pt[j * 64 + blk * 4 + ii] = p;
            }
        }
        __syncthreads();

        // ---- GEMM2: O[i][c] += P[i,k]*V[k,c], f32x2 packed along c, V = Ks
#pragma unroll 2
        for (int k = 0; k < 64; ++k) {
            int key = (k >> 2) & 7;
            int blk = ty ^ (k >> 2);                    // P^T read block
            float4 pv = *reinterpret_cast<const float4*>(Pt + k * 64 + blk * 4);
            int pc0 = tx ^ key;                         // cols tx*4..tx*4+3
            int pc1 = (16 + tx) ^ key;                  // cols 64+tx*4..64+tx*4+3
            ulonglong2 v0 = *reinterpret_cast<const ulonglong2*>(Ks + k * 128 + pc0 * 4);
            ulonglong2 v1 = *reinterpret_cast<const ulonglong2*>(Ks + k * 128 + pc1 * 4);
            unsigned long long pd[4];
            pd[0] = dup2(pv.x); pd[1] = dup2(pv.y);
            pd[2] = dup2(pv.z); pd[3] = dup2(pv.w);
#pragma unroll
            for (int ii = 0; ii < 4; ++ii) {
                ffma2(Oacc[ii][0], pd[ii], v0.x);
                ffma2(Oacc[ii][1], pd[ii], v0.y);
                ffma2(Oacc[ii][2], pd[ii], v1.x);
                ffma2(Oacc[ii][3], pd[ii], v1.y);
            }
        }
    }

    // ---- write O: rows ty*4+ii, col groups at tx*4 and 64+tx*4
#pragma unroll
    for (int ii = 0; ii < 4; ++ii) {
        int i = ty * 4 + ii;
        float* orow = out + ((size_t)slice * SEQ + qbase + i) * HD;
        float4 w0, w1;
        { float lo, hi;
          asm("mov.b64 {%0,%1}, %2;" : "=f"(lo), "=f"(hi) : "l"(Oacc[ii][0]));
          w0.x = lo; w0.y = hi;
          asm("mov.b64 {%0,%1}, %2;" : "=f"(lo), "=f"(hi) : "l"(Oacc[ii][1]));
          w0.z = lo; w0.w = hi;
          asm("mov.b64 {%0,%1}, %2;" : "=f"(lo), "=f"(hi) : "l"(Oacc[ii][2]));
          w1.x = lo; w1.y = hi;
          asm("mov.b64 {%0,%1}, %2;" : "=f"(lo), "=f"(hi) : "l"(Oacc[ii][3]));
          w1.z = lo; w1.w = hi; }
        *reinterpret_cast<float4*>(orow + tx * 4)      = w0;
        *reinterpret_cast<float4*>(orow + 64 + tx * 4) = w1;
    }
}

extern "C" void kernel_launch(void* const* d_in, const int* in_sizes, int n_in,
                              void* d_out, int out_size) {
    const float* x    = (const float*)d_in[0];
    const float* beta = (const float*)d_in[1];
    float* out        = (float*)d_out;

    norms_kernel<<<NSLICE * SEQ / 8, 256>>>(x);

    cudaFuncSetAttribute(cosatt_kernel,
                         cudaFuncAttributeMaxDynamicSharedMemorySize, 82432);
    dim3 grid(SEQ / BM, NSLICE);
    cosatt_kernel<<<grid, 256, 82432>>>(x, beta, out);
}

// round 5
// speedup vs baseline: 3.0758x; 3.0758x over previous
#include <cuda_runtime.h>
#include <cstdint>

#define NSLICE 64
#define SEQ    1024
#define HD     128
#define QT     128     // q rows per CTA
#define KTL    128     // k cols per tile
#define PQ     132     // smem pitches (floats)
#define PK     132
#define PP     132

__device__ float g_rnorms[NSLICE * SEQ];

// smem float offsets
#define SQ_OFF 0
#define SK_OFF (128 * PQ)              // 16896
#define SP_OFF (SK_OFF + 128 * PK)     // 33792
#define SN_OFF (SP_OFF + 128 * PP)     // 50688
#define SMEM_BYTES ((SN_OFF + 128) * 4)   // 203264

// ---------------- helpers ----------------
__device__ __forceinline__ uint32_t smem_u32(const void* p) {
    uint32_t a;
    asm("{ .reg .u64 t; cvta.to.shared.u64 t, %1; cvt.u32.u64 %0, t; }" : "=r"(a) : "l"(p));
    return a;
}
__device__ __forceinline__ uint32_t cvt_tf32(float f) {
    uint32_t r; asm("cvt.rna.tf32.f32 %0, %1;" : "=r"(r) : "f"(f)); return r;
}
__device__ __forceinline__ float tanhapx(float x) {
    float y; asm("tanh.approx.f32 %0, %1;" : "=f"(y) : "f"(x)); return y;
}
__device__ __forceinline__ void ldm_x4(uint32_t* r, uint32_t addr) {
    asm volatile("ldmatrix.sync.aligned.m8n8.x4.shared.b16 {%0,%1,%2,%3}, [%4];"
                 : "=r"(r[0]), "=r"(r[1]), "=r"(r[2]), "=r"(r[3]) : "r"(addr));
}
__device__ __forceinline__ void mma_tf32(float* c, const uint32_t* a,
                                         uint32_t b0, uint32_t b1) {
    asm volatile("mma.sync.aligned.m16n8k8.row.col.f32.tf32.tf32.f32 "
                 "{%0,%1,%2,%3}, {%4,%5,%6,%7}, {%8,%9}, {%0,%1,%2,%3};"
                 : "+f"(c[0]), "+f"(c[1]), "+f"(c[2]), "+f"(c[3])
                 : "r"(a[0]), "r"(a[1]), "r"(a[2]), "r"(a[3]), "r"(b0), "r"(b1));
}

// ---------------- reciprocal norms ----------------
__global__ __launch_bounds__(256) void rnorms_kernel(const float* __restrict__ x) {
    int row  = blockIdx.x * 8 + (threadIdx.x >> 5);
    int lane = threadIdx.x & 31;
    float4 v = reinterpret_cast<const float4*>(x + (size_t)row * HD)[lane];
    float s = v.x * v.x + v.y * v.y + v.z * v.z + v.w * v.w;
#pragma unroll
    for (int o = 16; o; o >>= 1) s += __shfl_xor_sync(0xffffffffu, s, o);
    if (lane == 0) g_rnorms[row] = rsqrtf(s);
}

// ---------------- fused cosine attention (tf32 mma.sync) ----------------
__global__ __launch_bounds__(256) void cosatt_mma_kernel(
    const float* __restrict__ x,
    const float* __restrict__ beta,
    float* __restrict__ out)
{
    extern __shared__ float sm[];
    float*    smQf = sm + SQ_OFF;
    uint32_t* smKu = reinterpret_cast<uint32_t*>(sm + SK_OFF);
    float*    knf  = sm + SN_OFF;
    const uint32_t smQ = smem_u32(sm + SQ_OFF);
    const uint32_t smK = smem_u32(sm + SK_OFF);
    const uint32_t smP = smem_u32(sm + SP_OFF);

    const int tid  = threadIdx.x;
    const int wid  = tid >> 5;
    const int lane = tid & 31;
    const int wr   = wid & 3;          // warp row (m)
    const int wc   = wid >> 2;         // warp col (n)
    const int m0   = wr * 32;
    const int n0   = wc * 64;
    const int slice = blockIdx.y;
    const int qbase = blockIdx.x * QT;

    const float* xs = x + (size_t)slice * SEQ * HD;

    // ---- prologue: Q tile (tf32 bits) + per-thread rq
    {
        const float4* src = reinterpret_cast<const float4*>(xs + (size_t)qbase * HD);
#pragma unroll
        for (int r = 0; r < 16; ++r) {
            int f = r * 256 + tid;
            int row = f >> 5, c4 = f & 31;
            float4 v = src[f];
            uint4 t = { cvt_tf32(v.x), cvt_tf32(v.y), cvt_tf32(v.z), cvt_tf32(v.w) };
            *reinterpret_cast<uint4*>(smQf + row * PQ + c4 * 4) = t;
        }
    }
    float rq[2][2];
#pragma unroll
    for (int mf = 0; mf < 2; ++mf)
#pragma unroll
        for (int h = 0; h < 2; ++h)
            rq[mf][h] = g_rnorms[slice * SEQ + qbase + m0 + mf * 16 + (lane >> 2) + h * 8];

    // ldmatrix lane addressing constants
    const int laneA_row = lane & 15;
    const int laneA_cg  = (lane >> 4) << 2;
    const int laneB_row = (lane & 7) + ((lane & 16) >> 1);
    const int laneB_cg  = (lane & 8) >> 1;

    uint32_t aBaseQ[2], aBaseP[2], bBaseK[4];
#pragma unroll
    for (int mf = 0; mf < 2; ++mf) {
        aBaseQ[mf] = smQ + ((m0 + mf * 16 + laneA_row) * PQ + laneA_cg) * 4;
        aBaseP[mf] = smP + ((m0 + mf * 16 + laneA_row) * PP + laneA_cg) * 4;
    }
#pragma unroll
    for (int g = 0; g < 4; ++g)
        bBaseK[g] = smK + ((n0 + g * 16 + laneB_row) * PK + laneB_cg) * 4;

    const int b2row = lane & 3;          // j-offset within kstep for GEMM2 B
    const int b2col = n0 + (lane >> 2);  // c col (n0 reused: output cols = wc*64)

    float oacc[2][8][4];
#pragma unroll
    for (int mf = 0; mf < 2; ++mf)
#pragma unroll
        for (int nf = 0; nf < 8; ++nf)
#pragma unroll
            for (int q = 0; q < 4; ++q) oacc[mf][nf][q] = 0.0f;

    for (int kt = 0; kt < SEQ / KTL; ++kt) {
        const int kbase = kt * KTL;
        __syncthreads();   // prior GEMM2 done with K/P

        // ---- load K tile (tf32 bits) + kn
        {
            const float4* src = reinterpret_cast<const float4*>(xs + (size_t)kbase * HD);
#pragma unroll
            for (int r = 0; r < 16; ++r) {
                int f = r * 256 + tid;
                int row = f >> 5, c4 = f & 31;
                float4 v = src[f];
                uint4 t = { cvt_tf32(v.x), cvt_tf32(v.y), cvt_tf32(v.z), cvt_tf32(v.w) };
                *reinterpret_cast<uint4*>(sm + SK_OFF + row * PK + c4 * 4) = t;
            }
            if (tid < 128) knf[tid] = g_rnorms[slice * SEQ + kbase + tid];
        }
        __syncthreads();

        // ---- GEMM1: S = Q . K^T  (warp tile 32 x 64)
        float sacc[2][8][4];
#pragma unroll
        for (int mf = 0; mf < 2; ++mf)
#pragma unroll
            for (int nf = 0; nf < 8; ++nf)
#pragma unroll
                for (int q = 0; q < 4; ++q) sacc[mf][nf][q] = 0.0f;

#pragma unroll
        for (int ks = 0; ks < 16; ++ks) {
            uint32_t a[2][4], b[4][4];
            ldm_x4(a[0], aBaseQ[0] + ks * 32);
            ldm_x4(a[1], aBaseQ[1] + ks * 32);
#pragma unroll
            for (int g = 0; g < 4; ++g) ldm_x4(b[g], bBaseK[g] + ks * 32);
#pragma unroll
            for (int mf = 0; mf < 2; ++mf)
#pragma unroll
                for (int g = 0; g < 4; ++g) {
                    mma_tf32(sacc[mf][2 * g],     a[mf], b[g][0], b[g][1]);
                    mma_tf32(sacc[mf][2 * g + 1], a[mf], b[g][2], b[g][3]);
                }
        }

        // ---- epilogue: P = sigmoid(beta * cos) -> smem (tf32 bits)
#pragma unroll
        for (int nf = 0; nf < 8; ++nf) {
            const int j0 = n0 + nf * 8 + ((lane & 3) << 1);   // tile-local k col
            const float2 rk = *reinterpret_cast<const float2*>(knf + j0);
#pragma unroll
            for (int mf = 0; mf < 2; ++mf) {
                const int r0 = m0 + mf * 16 + (lane >> 2);    // CTA-local q row
#pragma unroll
                for (int h = 0; h < 2; ++h) {
                    const int rr = r0 + h * 8;
                    const float2 bv = *reinterpret_cast<const float2*>(
                        beta + (size_t)(qbase + rr) * SEQ + kbase + j0);
                    const float rqv = rq[mf][h];
                    float z0 = sacc[mf][nf][2 * h]     * rqv * rk.x * bv.x;
                    float z1 = sacc[mf][nf][2 * h + 1] * rqv * rk.y * bv.y;
                    float p0 = 0.5f * tanhapx(0.5f * z0) + 0.5f;
                    float p1 = 0.5f * tanhapx(0.5f * z1) + 0.5f;
                    uint2 pw = { cvt_tf32(p0), cvt_tf32(p1) };
                    *reinterpret_cast<uint2*>(sm + SP_OFF + rr * PP + j0) = pw;
                }
            }
        }
        __syncthreads();   // P visible to all warps

        // ---- GEMM2: O += P . V  (warp tile 32 x 64, V = K tile row-major)
#pragma unroll
        for (int ks = 0; ks < 16; ++ks) {
            uint32_t a[2][4];
            ldm_x4(a[0], aBaseP[0] + ks * 32);
            ldm_x4(a[1], aBaseP[1] + ks * 32);
            const int jr = ks * 8 + b2row;
#pragma unroll
            for (int nf = 0; nf < 8; ++nf) {
                uint32_t b0 = smKu[jr * PK + b2col + nf * 8];
                uint32_t b1 = smKu[(jr + 4) * PK + b2col + nf * 8];
                mma_tf32(oacc[0][nf], a[0], b0, b1);
                mma_tf32(oacc[1][nf], a[1], b0, b1);
            }
        }
    }

    // ---- write O
#pragma unroll
    for (int mf = 0; mf < 2; ++mf)
#pragma unroll
        for (int h = 0; h < 2; ++h) {
            const int row = qbase + m0 + mf * 16 + (lane >> 2) + h * 8;
            float* orow = out + ((size_t)slice * SEQ + row) * HD;
#pragma unroll
            for (int nf = 0; nf < 8; ++nf) {
                const int col = n0 + nf * 8 + ((lane & 3) << 1);
                float2 w = { oacc[mf][nf][2 * h], oacc[mf][nf][2 * h + 1] };
                *reinterpret_cast<float2*>(orow + col) = w;
            }
        }
}

extern "C" void kernel_launch(void* const* d_in, const int* in_sizes, int n_in,
                              void* d_out, int out_size) {
    const float* x    = (const float*)d_in[0];
    const float* beta = (const float*)d_in[1];
    float* out        = (float*)d_out;

    rnorms_kernel<<<NSLICE * SEQ / 8, 256>>>(x);

    cudaFuncSetAttribute(cosatt_mma_kernel,
                         cudaFuncAttributeMaxDynamicSharedMemorySize, SMEM_BYTES);
    dim3 grid(SEQ / QT, NSLICE);
    cosatt_mma_kernel<<<grid, 256, SMEM_BYTES>>>(x, beta, out);
}